// round 10
// baseline (speedup 1.0000x reference)
#include <cuda_runtime.h>
#include <math.h>

#define NTOK 2048
#define CDIM 1024
#define FDIM 2816
#define EEXP 8
#define KTOP 2

// -------- device scratch (static: no allocations allowed) --------
__device__ int   g_cnt[EEXP];
__device__ int   g_bucket[EEXP][NTOK];          // entry ids (n*2+k)
__device__ float g_wgt[NTOK * KTOP];            // routing weight per entry
__device__ float g_H[(size_t)NTOK * KTOP * FDIM]; // 46 MB: silu(xW1)*(xW3) per entry

// ------------------------------------------------------------------
// Kernel 0: zero output y region + expert counters
// ------------------------------------------------------------------
__global__ void zero_kernel(float4* __restrict__ out)
{
    int i = blockIdx.x * blockDim.x + threadIdx.x;   // 524288 float4 = N*C floats
    out[i] = make_float4(0.f, 0.f, 0.f, 0.f);
    if (blockIdx.x == 0 && threadIdx.x < EEXP) g_cnt[threadIdx.x] = 0;
}

// ------------------------------------------------------------------
// Kernel 1: router — logits, top-2, softmax, bucket build, indices out
// ------------------------------------------------------------------
__global__ void router_kernel(const float* __restrict__ x,
                              const float* __restrict__ Wg,
                              float* __restrict__ out, int out_size)
{
    const int n = blockIdx.x;
    const float* xr = x + (size_t)n * CDIM;

    float part[EEXP];
#pragma unroll
    for (int e = 0; e < EEXP; ++e) part[e] = 0.f;

    for (int c = threadIdx.x; c < CDIM; c += blockDim.x) {
        float xv = xr[c];
        const float4* wrow = reinterpret_cast<const float4*>(Wg + (size_t)c * EEXP);
        float4 w0 = wrow[0], w1 = wrow[1];
        part[0] += xv * w0.x; part[1] += xv * w0.y;
        part[2] += xv * w0.z; part[3] += xv * w0.w;
        part[4] += xv * w1.x; part[5] += xv * w1.y;
        part[6] += xv * w1.z; part[7] += xv * w1.w;
    }

#pragma unroll
    for (int off = 16; off > 0; off >>= 1) {
#pragma unroll
        for (int e = 0; e < EEXP; ++e)
            part[e] += __shfl_down_sync(0xffffffff, part[e], off);
    }

    __shared__ float red[8][EEXP];
    const int warp = threadIdx.x >> 5, lane = threadIdx.x & 31;
    if (lane == 0) {
#pragma unroll
        for (int e = 0; e < EEXP; ++e) red[warp][e] = part[e];
    }
    __syncthreads();

    if (threadIdx.x == 0) {
        float r[EEXP];
#pragma unroll
        for (int e = 0; e < EEXP; ++e) {
            float s = 0.f;
#pragma unroll
            for (int w = 0; w < 8; ++w) s += red[w][e];
            r[e] = s;
        }
        // top-2, descending; strict > keeps lowest index on ties (matches top_k)
        int i0 = 0;
#pragma unroll
        for (int e = 1; e < EEXP; ++e) if (r[e] > r[i0]) i0 = e;
        int i1 = -1;
#pragma unroll
        for (int e = 0; e < EEXP; ++e)
            if (e != i0 && (i1 < 0 || r[e] > r[i1])) i1 = e;

        // softmax over the 2 selected logits (r[i0] is the max)
        float e1 = __expf(r[i1] - r[i0]);
        float inv = 1.f / (1.f + e1);
        float p0 = inv;
        float p1 = e1 * inv;

        int ent0 = n * 2 + 0, ent1 = n * 2 + 1;
        g_wgt[ent0] = p0;
        g_wgt[ent1] = p1;
        int pos0 = atomicAdd(&g_cnt[i0], 1);
        g_bucket[i0][pos0] = ent0;
        int pos1 = atomicAdd(&g_cnt[i1], 1);
        g_bucket[i1][pos1] = ent1;

        // second output (indices) appended after y, if the buffer carries it
        if (out_size >= NTOK * CDIM + NTOK * KTOP) {
            out[NTOK * CDIM + ent0] = (float)i0;
            out[NTOK * CDIM + ent1] = (float)i1;
        }
    }
}

// ------------------------------------------------------------------
// GEMM tiling config (shared by both stages)
// ------------------------------------------------------------------
#define BM 128
#define BN 64
#define BK 8
#define TM 8
#define TN 4
// 256 threads: 16x16; thread computes TM x TN micro-tile

// ------------------------------------------------------------------
// Kernel 2: Stage A — H[ent, f] = silu(x@W1[e]) * (x@W3[e]) for bucket rows
// grid: (FDIM/BN, NTOK/BM, EEXP), early-exit on m-tiles beyond count
// ------------------------------------------------------------------
__global__ void stageA_kernel(const float* __restrict__ x,
                              const float* __restrict__ W1,
                              const float* __restrict__ W3)
{
    const int e   = blockIdx.z;
    const int cnt = g_cnt[e];
    const int m0  = blockIdx.y * BM;
    if (m0 >= cnt) return;
    const int f0  = blockIdx.x * BN;

    __shared__ float As [2][BK][BM];
    __shared__ float Bs1[2][BK][BN];
    __shared__ float Bs3[2][BK][BN];
    __shared__ int   s_ent[BM];
    __shared__ int   s_tok[BM];

    const int tid = threadIdx.x;
    if (tid < BM) {
        int r   = m0 + tid;
        int ent = (r < cnt) ? g_bucket[e][r] : -1;
        s_ent[tid] = ent;
        s_tok[tid] = (ent >= 0) ? (ent >> 1) : 0;
    }
    __syncthreads();

    const float* W1e = W1 + (size_t)e * CDIM * FDIM + f0;
    const float* W3e = W3 + (size_t)e * CDIM * FDIM + f0;

    // A-tile loader mapping: 256 threads -> 128 rows x 2 float4-cols (BK=8)
    const int rowA = tid >> 1;
    const int colA = (tid & 1) * 4;
    const float* xrowA = x + (size_t)s_tok[rowA] * CDIM + colA;

    // B-tile loader mapping: lower 128 threads load W1 tile, upper 128 load W3
    const int bHalf = (tid >= 128);
    const int t2    = tid & 127;
    const int rowB  = t2 >> 4;          // 0..7
    const int colB  = (t2 & 15) * 4;    // 0..60
    const float* Wsrc = bHalf ? W3e : W1e;

    const int tRow = (tid >> 4) * TM;
    const int tCol = (tid & 15) * TN;

    float acc1[TM][TN], acc3[TM][TN];
#pragma unroll
    for (int i = 0; i < TM; ++i)
#pragma unroll
        for (int j = 0; j < TN; ++j) { acc1[i][j] = 0.f; acc3[i][j] = 0.f; }

    // prologue: stage 0 into buffer 0
    {
        float4 av = *reinterpret_cast<const float4*>(xrowA);
        As[0][colA + 0][rowA] = av.x; As[0][colA + 1][rowA] = av.y;
        As[0][colA + 2][rowA] = av.z; As[0][colA + 3][rowA] = av.w;
        float4 bv = *reinterpret_cast<const float4*>(Wsrc + (size_t)rowB * FDIM + colB);
        float* bdst = (bHalf ? &Bs3[0][0][0] : &Bs1[0][0][0]) + rowB * BN + colB;
        *reinterpret_cast<float4*>(bdst) = bv;
    }
    __syncthreads();

    const int KT = CDIM / BK;
    int buf = 0;
    for (int kt = 0; kt < KT; ++kt) {
        const int nbuf = buf ^ 1;
        if (kt + 1 < KT) {
            const int k0 = (kt + 1) * BK;
            float4 av = *reinterpret_cast<const float4*>(xrowA + k0);
            As[nbuf][colA + 0][rowA] = av.x; As[nbuf][colA + 1][rowA] = av.y;
            As[nbuf][colA + 2][rowA] = av.z; As[nbuf][colA + 3][rowA] = av.w;
            float4 bv = *reinterpret_cast<const float4*>(
                Wsrc + (size_t)(k0 + rowB) * FDIM + colB);
            float* bdst = (bHalf ? &Bs3[nbuf][0][0] : &Bs1[nbuf][0][0]) + rowB * BN + colB;
            *reinterpret_cast<float4*>(bdst) = bv;
        }
#pragma unroll
        for (int kk = 0; kk < BK; ++kk) {
            float4 a01 = *reinterpret_cast<const float4*>(&As[buf][kk][tRow]);
            float4 a23 = *reinterpret_cast<const float4*>(&As[buf][kk][tRow + 4]);
            float4 b1  = *reinterpret_cast<const float4*>(&Bs1[buf][kk][tCol]);
            float4 b3  = *reinterpret_cast<const float4*>(&Bs3[buf][kk][tCol]);
            float a[TM] = {a01.x, a01.y, a01.z, a01.w, a23.x, a23.y, a23.z, a23.w};
            float vb1[TN] = {b1.x, b1.y, b1.z, b1.w};
            float vb3[TN] = {b3.x, b3.y, b3.z, b3.w};
#pragma unroll
            for (int i = 0; i < TM; ++i)
#pragma unroll
                for (int j = 0; j < TN; ++j) {
                    acc1[i][j] += a[i] * vb1[j];
                    acc3[i][j] += a[i] * vb3[j];
                }
        }
        __syncthreads();
        buf = nbuf;
    }

    // epilogue: fused SwiGLU, vectorized store to H
#pragma unroll
    for (int i = 0; i < TM; ++i) {
        int ent = s_ent[tRow + i];
        if (ent >= 0) {
            float4 hv;
            float v;
            v = acc1[i][0]; hv.x = v / (1.f + __expf(-v)) * acc3[i][0];
            v = acc1[i][1]; hv.y = v / (1.f + __expf(-v)) * acc3[i][1];
            v = acc1[i][2]; hv.z = v / (1.f + __expf(-v)) * acc3[i][2];
            v = acc1[i][3]; hv.w = v / (1.f + __expf(-v)) * acc3[i][3];
            *reinterpret_cast<float4*>(g_H + (size_t)ent * FDIM + f0 + tCol) = hv;
        }
    }
}

// ------------------------------------------------------------------
// Kernel 3: Stage B — y[token] += w_ent * (H[ent] @ W2[e])
// grid: (CDIM/BN, NTOK/BM, EEXP)
// ------------------------------------------------------------------
__global__ void stageB_kernel(const float* __restrict__ W2,
                              float* __restrict__ out)
{
    const int e   = blockIdx.z;
    const int cnt = g_cnt[e];
    const int m0  = blockIdx.y * BM;
    if (m0 >= cnt) return;
    const int c0  = blockIdx.x * BN;

    __shared__ float As[2][BK][BM];
    __shared__ float Bs[2][BK][BN];
    __shared__ int   s_ent[BM];

    const int tid = threadIdx.x;
    if (tid < BM) {
        int r = m0 + tid;
        s_ent[tid] = (r < cnt) ? g_bucket[e][r] : -1;
    }
    __syncthreads();

    const float* W2e = W2 + (size_t)e * FDIM * CDIM + c0;

    const int rowA = tid >> 1;
    const int colA = (tid & 1) * 4;
    int entA = s_ent[rowA];
    const float* hrowA = g_H + (size_t)((entA >= 0) ? entA : 0) * FDIM + colA;

    const int rowB = tid >> 5;          // 0..7
    const int colB = (tid & 31) * 4;    // wait: BN=64 -> need 16 cols of f4
    // remap: 256 threads over 8 rows x 16 float4-cols needs only 128 threads;
    // use two rows per thread-halfwave instead:
    const int rowB2 = tid >> 4;         // 0..15 but BK=8 -> fold
    (void)rowB; (void)colB; (void)rowB2;

    const int t2   = tid & 127;
    const int brow = t2 >> 4;           // 0..7
    const int bcol = (t2 & 15) * 4;     // 0..60
    const bool doB = (tid < 128);       // only 128 threads load B tile

    const int tRow = (tid >> 4) * TM;
    const int tCol = (tid & 15) * TN;

    float acc[TM][TN];
#pragma unroll
    for (int i = 0; i < TM; ++i)
#pragma unroll
        for (int j = 0; j < TN; ++j) acc[i][j] = 0.f;

    {
        float4 av = *reinterpret_cast<const float4*>(hrowA);
        As[0][colA + 0][rowA] = av.x; As[0][colA + 1][rowA] = av.y;
        As[0][colA + 2][rowA] = av.z; As[0][colA + 3][rowA] = av.w;
        if (doB) {
            float4 bv = *reinterpret_cast<const float4*>(W2e + (size_t)brow * CDIM + bcol);
            *reinterpret_cast<float4*>(&Bs[0][brow][bcol]) = bv;
        }
    }
    __syncthreads();

    const int KT = FDIM / BK;   // 352
    int buf = 0;
    for (int kt = 0; kt < KT; ++kt) {
        const int nbuf = buf ^ 1;
        if (kt + 1 < KT) {
            const int k0 = (kt + 1) * BK;
            float4 av = *reinterpret_cast<const float4*>(hrowA + k0);
            As[nbuf][colA + 0][rowA] = av.x; As[nbuf][colA + 1][rowA] = av.y;
            As[nbuf][colA + 2][rowA] = av.z; As[nbuf][colA + 3][rowA] = av.w;
            if (doB) {
                float4 bv = *reinterpret_cast<const float4*>(
                    W2e + (size_t)(k0 + brow) * CDIM + bcol);
                *reinterpret_cast<float4*>(&Bs[nbuf][brow][bcol]) = bv;
            }
        }
#pragma unroll
        for (int kk = 0; kk < BK; ++kk) {
            float4 a01 = *reinterpret_cast<const float4*>(&As[buf][kk][tRow]);
            float4 a23 = *reinterpret_cast<const float4*>(&As[buf][kk][tRow + 4]);
            float4 b   = *reinterpret_cast<const float4*>(&Bs[buf][kk][tCol]);
            float a[TM] = {a01.x, a01.y, a01.z, a01.w, a23.x, a23.y, a23.z, a23.w};
            float vb[TN] = {b.x, b.y, b.z, b.w};
#pragma unroll
            for (int i = 0; i < TM; ++i)
#pragma unroll
                for (int j = 0; j < TN; ++j)
                    acc[i][j] += a[i] * vb[j];
        }
        __syncthreads();
        buf = nbuf;
    }

    // epilogue: weighted scatter-add (exactly 2 fp32 adds per y element -> deterministic)
#pragma unroll
    for (int i = 0; i < TM; ++i) {
        int ent = s_ent[tRow + i];
        if (ent >= 0) {
            int   token = ent >> 1;
            float w     = g_wgt[ent];
            float* dst  = out + (size_t)token * CDIM + c0 + tCol;
            atomicAdd(dst + 0, w * acc[i][0]);
            atomicAdd(dst + 1, w * acc[i][1]);
            atomicAdd(dst + 2, w * acc[i][2]);
            atomicAdd(dst + 3, w * acc[i][3]);
        }
    }
}

// ------------------------------------------------------------------
extern "C" void kernel_launch(void* const* d_in, const int* in_sizes, int n_in,
                              void* d_out, int out_size)
{
    const float* x  = (const float*)d_in[0];   // [2,1024,1024]
    const float* Wg = (const float*)d_in[1];   // [1024,8]
    const float* W1 = (const float*)d_in[2];   // [8,1024,2816]
    const float* W3 = (const float*)d_in[3];   // [8,1024,2816]
    const float* W2 = (const float*)d_in[4];   // [8,2816,1024]
    float* out = (float*)d_out;

    // 1) zero y region + counters
    zero_kernel<<<(NTOK * CDIM / 4) / 256, 256>>>((float4*)out);

    // 2) router + bucket build (+ indices output tail)
    router_kernel<<<NTOK, 256>>>(x, Wg, out, out_size);

    // 3) stage A: gathered fused SwiGLU GEMM
    dim3 ga(FDIM / BN, NTOK / BM, EEXP);   // (44, 16, 8)
    stageA_kernel<<<ga, 256>>>(x, W1, W3);

    // 4) stage B: down-proj GEMM + weighted scatter
    dim3 gb(CDIM / BN, NTOK / BM, EEXP);   // (16, 16, 8)
    stageB_kernel<<<gb, 256>>>(W2, out);
}